// round 15
// baseline (speedup 1.0000x reference)
#include <cuda_runtime.h>
#include <math.h>
#include <stdint.h>

// Problem shapes (fixed)
#define NTOK 4096
#define HDIM 2048
#define NEXP 16
#define TOPK 4
#define IMOE 1408
#define ISH  5632
#define NSLOT (NTOK*TOPK)

// ---------------- scratch (device globals) ----------------
__device__ float g_Gr[(size_t)NSLOT * IMOE];
__device__ float g_Ur[(size_t)NSLOT * IMOE];
__device__ float g_Dr[(size_t)NSLOT * HDIM];
__device__ float g_Gs[(size_t)NTOK * ISH];
__device__ float g_Us[(size_t)NTOK * ISH];
__device__ float g_Ss[(size_t)NTOK * HDIM];
__device__ float g_sg[NTOK];
__device__ int   g_topk_idx[NSLOT];
__device__ float g_topk_w[NSLOT];
__device__ int   g_cnt[NEXP];
__device__ int   g_off[NEXP + 1];
__device__ int   g_fill[NEXP];
__device__ int   g_tok[NSLOT];
__device__ int   g_slotof[NSLOT];
// pre-rounded copies; weights also TRANSPOSED to [Ncols][K] (n-major)
__device__ float g_hr [(size_t)NTOK * HDIM];
__device__ float g_wg [(size_t)NEXP * IMOE * HDIM];   // [E][I][H]
__device__ float g_wu [(size_t)NEXP * IMOE * HDIM];   // [E][I][H]
__device__ float g_wd [(size_t)NEXP * HDIM * IMOE];   // [E][H][I]
__device__ float g_shg[(size_t)ISH * HDIM];           // [ISH][H]
__device__ float g_shu[(size_t)ISH * HDIM];           // [ISH][H]
__device__ float g_shd[(size_t)HDIM * ISH];           // [H][ISH]

// ---------------- helpers ----------------
#define SWZ(off) ((off) ^ (((off) >> 3) & 0x70))

__device__ __forceinline__ uint32_t smem_u32(const void* p) {
    uint32_t a;
    asm("{ .reg .u64 t; cvta.to.shared.u64 t, %1; cvt.u32.u64 %0, t; }" : "=r"(a) : "l"(p));
    return a;
}
__device__ __forceinline__ void ldsm4(uint32_t* r, uint32_t addr) {
    asm volatile("ldmatrix.sync.aligned.m8n8.x4.shared.b16 {%0,%1,%2,%3}, [%4];"
                 : "=r"(r[0]), "=r"(r[1]), "=r"(r[2]), "=r"(r[3]) : "r"(addr));
}
__device__ __forceinline__ void mma_tf32(float* c, const uint32_t* a, uint32_t b0, uint32_t b1) {
    asm volatile("mma.sync.aligned.m16n8k8.row.col.f32.tf32.tf32.f32 "
                 "{%0,%1,%2,%3}, {%4,%5,%6,%7}, {%8,%9}, {%0,%1,%2,%3};"
                 : "+f"(c[0]), "+f"(c[1]), "+f"(c[2]), "+f"(c[3])
                 : "r"(a[0]), "r"(a[1]), "r"(a[2]), "r"(a[3]), "r"(b0), "r"(b1));
}
__device__ __forceinline__ void cpa16(uint32_t dst, const void* src) {
    asm volatile("cp.async.cg.shared.global [%0], [%1], 16;" :: "r"(dst), "l"(src));
}
#define CPA_COMMIT() asm volatile("cp.async.commit_group;" ::: "memory")
#define CPA_WAIT2()  asm volatile("cp.async.wait_group 2;" ::: "memory")

// ---------------- small kernels ----------------
__global__ void init_kernel() {
    int t = threadIdx.x;
    if (t < NEXP) { g_cnt[t] = 0; g_fill[t] = 0; }
}

// round only (for h)
__global__ void round_kernel(const float* __restrict__ src, float* __restrict__ dst) {
    size_t i = (size_t)blockIdx.x * blockDim.x + threadIdx.x;
    uint4 v = ((const uint4*)src)[i];
    v.x += 0x1000u; v.y += 0x1000u; v.z += 0x1000u; v.w += 0x1000u;
    ((uint4*)dst)[i] = v;
}

// transpose [R,C] -> [C,R] per z-matrix, with tf32-RN bit rounding
__global__ void tround_kernel(const float* __restrict__ src, float* __restrict__ dst,
                              int R, int C) {
    __shared__ uint32_t tile[32][33];
    size_t mat = (size_t)blockIdx.z * (size_t)R * (size_t)C;
    int c0 = blockIdx.x * 32, r0 = blockIdx.y * 32;
    const uint32_t* s = (const uint32_t*)src + mat;
    uint32_t* d = (uint32_t*)dst + mat;
    int tx = threadIdx.x, ty = threadIdx.y;   // 32 x 8
    #pragma unroll
    for (int i = 0; i < 4; i++) {
        int r = r0 + ty + i * 8;
        tile[ty + i * 8][tx] = s[(size_t)r * C + c0 + tx] + 0x1000u;
    }
    __syncthreads();
    #pragma unroll
    for (int i = 0; i < 4; i++) {
        int c = c0 + ty + i * 8;
        d[(size_t)c * R + r0 + tx] = tile[tx][ty + i * 8];
    }
}

__global__ void router_kernel(const float* __restrict__ h, const float* __restrict__ rw) {
    __shared__ float sh[HDIM];
    __shared__ float lg[NEXP];
    int n = blockIdx.x;
    int tid = threadIdx.x;
    const float* hp = h + (size_t)n * HDIM;
    for (int i = tid; i < HDIM; i += 128) sh[i] = hp[i];
    __syncthreads();
    int w = tid >> 5, lane = tid & 31;
    for (int e = w; e < NEXP; e += 4) {
        const float* r = rw + (size_t)e * HDIM;
        float s = 0.f;
        for (int i = lane; i < HDIM; i += 32) s += sh[i] * r[i];
        #pragma unroll
        for (int o = 16; o; o >>= 1) s += __shfl_xor_sync(0xffffffff, s, o);
        if (lane == 0) lg[e] = s;
    }
    __syncthreads();
    if (tid == 0) {
        float m = -1e30f;
        for (int e = 0; e < NEXP; e++) m = fmaxf(m, lg[e]);
        float p[NEXP]; float sum = 0.f;
        for (int e = 0; e < NEXP; e++) { p[e] = expf(lg[e] - m); sum += p[e]; }
        float inv = 1.f / sum;
        for (int e = 0; e < NEXP; e++) p[e] *= inv;
        int idx[TOPK]; float val[TOPK]; float tot = 0.f;
        for (int k = 0; k < TOPK; k++) {
            float best = -1.f; int bi = 0;
            for (int e = 0; e < NEXP; e++) if (p[e] > best) { best = p[e]; bi = e; }
            idx[k] = bi; val[k] = best; p[bi] = -2.f; tot += best;
        }
        float invt = 1.f / fmaxf(tot, 1e-9f);
        for (int k = 0; k < TOPK; k++) {
            g_topk_idx[n * TOPK + k] = idx[k];
            g_topk_w[n * TOPK + k]   = val[k] * invt;
            atomicAdd(&g_cnt[idx[k]], 1);
        }
    }
}

__global__ void offsets_kernel() {
    if (threadIdx.x == 0) {
        int acc = 0;
        for (int e = 0; e < NEXP; e++) { g_off[e] = acc; acc += g_cnt[e]; }
        g_off[NEXP] = acc;
    }
}

__global__ void scatter_kernel() {
    int i = blockIdx.x * blockDim.x + threadIdx.x;
    if (i >= NSLOT) return;
    int e = g_topk_idx[i];
    int pos = g_off[e] + atomicAdd(&g_fill[e], 1);
    g_tok[pos]  = i / TOPK;
    g_slotof[i] = pos;
}

// ---------------- tf32 mma.sync GEMM, cp.async 4-stage, B pre-transposed ----------------
// C[M,Ncols] = A[M,K] @ B^T where B stored [Ncols][K] (n-major).
// Block tile 256x128x32, 8 warps (4x2), warp tile 64x64 via m16n8k8 tf32 mma.
template <bool GATHER, bool EXPERT>
__global__ void __launch_bounds__(256, 1)
mmagemm(const float* __restrict__ A, const float* __restrict__ B0, const float* __restrict__ B1,
        float* __restrict__ C0, float* __restrict__ C1, int Ncols, int K, int Mtot)
{
    extern __shared__ char smraw[];
    constexpr uint32_t STG = 49152u;
    int tid = threadIdx.x, lane = tid & 31, wid = tid >> 5;
    int wm = wid >> 1, wn = wid & 1;   // 4 x 2 warp grid, warp tile 64x64

    int e    = EXPERT ? blockIdx.z : 0;
    int base = EXPERT ? g_off[e] : 0;
    int M    = EXPERT ? (g_off[e + 1] - base) : Mtot;
    int m0   = blockIdx.y * 256;
    if (m0 >= M) return;
    int ntiles = Ncols / 128;
    int sel    = blockIdx.x / ntiles;
    long n0    = (long)(blockIdx.x % ntiles) * 128;
    const float* B = sel ? B1 : B0;
    if (EXPERT) B += (size_t)e * (size_t)K * (size_t)Ncols;
    float* C = sel ? C1 : C0;

    uint32_t sb = (smem_u32(smraw) + 1023u) & ~1023u;

    // ---- producer mappings (all 16B cp.async along k)
    int rbase = tid >> 3;               // 0..31
    int akq   = (tid & 7);              // 16B chunk index along k
    int arows[8];
    #pragma unroll
    for (int r = 0; r < 8; r++) {
        int row = m0 + rbase + 32 * r;
        row = row < M ? row : (M - 1);
        arows[r] = GATHER ? g_tok[base + row] : (base + row);
    }
    const float* Bbase = B + (size_t)n0 * K;   // tile rows n-major

    int nst = K >> 5;
    float acc[4][8][4];
    #pragma unroll
    for (int i = 0; i < 4; i++)
        #pragma unroll
        for (int j = 0; j < 8; j++)
            #pragma unroll
            for (int q = 0; q < 4; q++) acc[i][j][q] = 0.f;

    auto fill = [&](int s, int it) {
        uint32_t aB = sb + (uint32_t)s * STG;
        uint32_t bB = aB + 32768u;
        int k0 = it << 5;
        #pragma unroll
        for (int r = 0; r < 8; r++) {
            const float* src = A + (size_t)arows[r] * K + k0 + akq * 4;
            uint32_t dst = aB + SWZ((uint32_t)((rbase + 32 * r) * 128 + akq * 16));
            cpa16(dst, src);
        }
        #pragma unroll
        for (int r = 0; r < 4; r++) {
            int row = rbase + 32 * r;   // 0..127
            const float* src = Bbase + (size_t)row * K + k0 + akq * 4;
            uint32_t dst = bB + SWZ((uint32_t)(row * 128 + akq * 16));
            cpa16(dst, src);
        }
    };

    // prefill 3 stages
    fill(0, 0); CPA_COMMIT();
    if (nst > 1) fill(1, 1);
    CPA_COMMIT();
    if (nst > 2) fill(2, 2);
    CPA_COMMIT();

    for (int it = 0; it < nst; it++) {
        int s = it & 3;
        CPA_WAIT2();
        __syncthreads();
        if (it + 3 < nst) fill((it + 3) & 3, it + 3);
        CPA_COMMIT();

        uint32_t aB = sb + (uint32_t)s * STG;
        uint32_t bB = aB + 32768u;
        #pragma unroll
        for (int ks = 0; ks < 4; ks++) {
            uint32_t af[4][4];
            #pragma unroll
            for (int mf = 0; mf < 4; mf++) {
                uint32_t row = (uint32_t)(wm * 64 + mf * 16 + (lane & 15));
                uint32_t off = row * 128 + (uint32_t)ks * 32 + ((lane >> 4) * 16);
                ldsm4(af[mf], aB + SWZ(off));
            }
            uint32_t bf[4][4];
            #pragma unroll
            for (int j = 0; j < 4; j++) {
                uint32_t row = (uint32_t)(wn * 64 + j * 16 + (lane & 7) + ((lane >> 4) << 3));
                uint32_t off = row * 128 + (uint32_t)ks * 32 + (((lane >> 3) & 1) * 16);
                ldsm4(bf[j], bB + SWZ(off));
            }
            #pragma unroll
            for (int mf = 0; mf < 4; mf++)
                #pragma unroll
                for (int nf = 0; nf < 8; nf++)
                    mma_tf32(acc[mf][nf], af[mf], bf[nf >> 1][(nf & 1) * 2],
                             bf[nf >> 1][(nf & 1) * 2 + 1]);
        }
    }

    // ---- epilogue
    #pragma unroll
    for (int mf = 0; mf < 4; mf++) {
        int r0 = m0 + wm * 64 + mf * 16 + (lane >> 2);
        #pragma unroll
        for (int nf = 0; nf < 8; nf++) {
            long col = n0 + wn * 64 + nf * 8 + (lane & 3) * 2;
            float* cp = C + (size_t)(base + r0) * Ncols + col;
            if (r0 < M)     *(float2*)cp                       = make_float2(acc[mf][nf][0], acc[mf][nf][1]);
            if (r0 + 8 < M) *(float2*)(cp + (size_t)8 * Ncols) = make_float2(acc[mf][nf][2], acc[mf][nf][3]);
        }
    }
}

// ---------------- elementwise ----------------
__global__ void silu_mul_kernel(float* __restrict__ g, const float* __restrict__ u, size_t nelem) {
    size_t i = ((size_t)blockIdx.x * blockDim.x + threadIdx.x) * 4;
    if (i >= nelem) return;
    float4 gv = *(const float4*)(g + i);
    float4 uv = *(const float4*)(u + i);
    uint4 o;
    o.x = __float_as_uint(gv.x / (1.f + expf(-gv.x)) * uv.x) + 0x1000u;
    o.y = __float_as_uint(gv.y / (1.f + expf(-gv.y)) * uv.y) + 0x1000u;
    o.z = __float_as_uint(gv.z / (1.f + expf(-gv.z)) * uv.z) + 0x1000u;
    o.w = __float_as_uint(gv.w / (1.f + expf(-gv.w)) * uv.w) + 0x1000u;
    *(uint4*)(g + i) = o;
}

__global__ void sgate_kernel(const float* __restrict__ h, const float* __restrict__ w) {
    int gt = blockIdx.x * blockDim.x + threadIdx.x;
    int n = gt >> 5, lane = gt & 31;
    if (n >= NTOK) return;
    const float* hp = h + (size_t)n * HDIM;
    float s = 0.f;
    for (int i = lane; i < HDIM; i += 32) s = fmaf(hp[i], w[i], s);
    #pragma unroll
    for (int o = 16; o; o >>= 1) s += __shfl_xor_sync(0xffffffff, s, o);
    if (lane == 0) g_sg[n] = 1.f / (1.f + expf(-s));
}

__global__ void combine_kernel(float* __restrict__ out) {
    int n = blockIdx.x;
    __shared__ int   ss[TOPK];
    __shared__ float ww[TOPK];
    __shared__ float sgv;
    if (threadIdx.x < TOPK) {
        ss[threadIdx.x] = g_slotof[n * TOPK + threadIdx.x];
        ww[threadIdx.x] = g_topk_w[n * TOPK + threadIdx.x];
    }
    if (threadIdx.x == 0) sgv = g_sg[n];
    __syncthreads();
    const float4* d0 = (const float4*)(g_Dr + (size_t)ss[0] * HDIM);
    const float4* d1 = (const float4*)(g_Dr + (size_t)ss[1] * HDIM);
    const float4* d2 = (const float4*)(g_Dr + (size_t)ss[2] * HDIM);
    const float4* d3 = (const float4*)(g_Dr + (size_t)ss[3] * HDIM);
    const float4* sh = (const float4*)(g_Ss + (size_t)n * HDIM);
    float4* op = (float4*)(out + (size_t)n * HDIM);
    float w0 = ww[0], w1 = ww[1], w2 = ww[2], w3 = ww[3], s = sgv;
    for (int j = threadIdx.x; j < HDIM / 4; j += blockDim.x) {
        float4 a = d0[j], b = d1[j], c = d2[j], d = d3[j], e2 = sh[j];
        float4 r;
        r.x = w0 * a.x + w1 * b.x + w2 * c.x + w3 * d.x + s * e2.x;
        r.y = w0 * a.y + w1 * b.y + w2 * c.y + w3 * d.y + s * e2.y;
        r.z = w0 * a.z + w1 * b.z + w2 * c.z + w3 * d.z + s * e2.z;
        r.w = w0 * a.w + w1 * b.w + w2 * c.w + w3 * d.w + s * e2.w;
        op[j] = r;
    }
}

// ---------------- launch ----------------
extern "C" void kernel_launch(void* const* d_in, const int* in_sizes, int n_in,
                              void* d_out, int out_size) {
    const float* h   = (const float*)d_in[0];
    const float* rw  = (const float*)d_in[1];
    const float* wg  = (const float*)d_in[2];
    const float* wu  = (const float*)d_in[3];
    const float* wd  = (const float*)d_in[4];
    const float* shg = (const float*)d_in[5];
    const float* shu = (const float*)d_in[6];
    const float* shd = (const float*)d_in[7];
    const float* sgw = (const float*)d_in[8];
    float* out = (float*)d_out;

    float *pGr, *pUr, *pDr, *pGs, *pUs, *pSs, *pHr;
    float *pWg, *pWu, *pWd, *pSg, *pSu, *pSd;
    cudaGetSymbolAddress((void**)&pGr, g_Gr);
    cudaGetSymbolAddress((void**)&pUr, g_Ur);
    cudaGetSymbolAddress((void**)&pDr, g_Dr);
    cudaGetSymbolAddress((void**)&pGs, g_Gs);
    cudaGetSymbolAddress((void**)&pUs, g_Us);
    cudaGetSymbolAddress((void**)&pSs, g_Ss);
    cudaGetSymbolAddress((void**)&pHr, g_hr);
    cudaGetSymbolAddress((void**)&pWg, g_wg);
    cudaGetSymbolAddress((void**)&pWu, g_wu);
    cudaGetSymbolAddress((void**)&pWd, g_wd);
    cudaGetSymbolAddress((void**)&pSg, g_shg);
    cudaGetSymbolAddress((void**)&pSu, g_shu);
    cudaGetSymbolAddress((void**)&pSd, g_shd);

    const int SMB = 4 * 49152 + 1024;  // 197632 (4-stage)
    cudaFuncSetAttribute(mmagemm<true,  true >, cudaFuncAttributeMaxDynamicSharedMemorySize, SMB);
    cudaFuncSetAttribute(mmagemm<false, true >, cudaFuncAttributeMaxDynamicSharedMemorySize, SMB);
    cudaFuncSetAttribute(mmagemm<false, false>, cudaFuncAttributeMaxDynamicSharedMemorySize, SMB);

    // Pre-round h; pre-round + transpose all weight matrices to [Ncols][K]
    {
        const size_t NH = (size_t)NTOK * HDIM;
        round_kernel<<<(unsigned)(NH / 4 / 256), 256>>>(h, pHr);
        dim3 thr(32, 8);
        tround_kernel<<<dim3(IMOE / 32, HDIM / 32, NEXP), thr>>>(wg,  pWg, HDIM, IMOE);
        tround_kernel<<<dim3(IMOE / 32, HDIM / 32, NEXP), thr>>>(wu,  pWu, HDIM, IMOE);
        tround_kernel<<<dim3(HDIM / 32, IMOE / 32, NEXP), thr>>>(wd,  pWd, IMOE, HDIM);
        tround_kernel<<<dim3(ISH / 32,  HDIM / 32, 1),    thr>>>(shg, pSg, HDIM, ISH);
        tround_kernel<<<dim3(ISH / 32,  HDIM / 32, 1),    thr>>>(shu, pSu, HDIM, ISH);
        tround_kernel<<<dim3(HDIM / 32, ISH / 32,  1),    thr>>>(shd, pSd, ISH,  HDIM);
    }

    // Router pipeline
    init_kernel<<<1, 32>>>();
    router_kernel<<<NTOK, 128>>>(h, rw);
    offsets_kernel<<<1, 1>>>();
    scatter_kernel<<<NSLOT / 256, 256>>>();

    // Routed experts: fused gate+up (gathered A), SwiGLU, down
    {
        dim3 g(2 * (IMOE / 128), 16, NEXP);   // (22, 16, 16)
        mmagemm<true, true><<<g, 256, SMB>>>(pHr, pWg, pWu, pGr, pUr, IMOE, HDIM, 0);
    }
    {
        size_t ne = (size_t)NSLOT * IMOE;
        silu_mul_kernel<<<(unsigned)(ne / 4 / 256), 256>>>(pGr, pUr, ne);
    }
    {
        dim3 g(HDIM / 128, 16, NEXP);         // (16, 16, 16)
        mmagemm<false, true><<<g, 256, SMB>>>(pGr, pWd, pWd, pDr, pDr, HDIM, IMOE, 0);
    }

    // Shared expert: fused gate+up, SwiGLU, down
    {
        dim3 g(2 * (ISH / 128), NTOK / 256, 1);   // (88, 16, 1)
        mmagemm<false, false><<<g, 256, SMB>>>(pHr, pSg, pSu, pGs, pUs, ISH, HDIM, NTOK);
    }
    {
        size_t ne = (size_t)NTOK * ISH;
        silu_mul_kernel<<<(unsigned)(ne / 4 / 256), 256>>>(pGs, pUs, ne);
    }
    {
        dim3 g(HDIM / 128, NTOK / 256, 1);    // (16, 16, 1)
        mmagemm<false, false><<<g, 256, SMB>>>(pGs, pSd, pSd, pSs, pSs, HDIM, ISH, NTOK);
    }

    sgate_kernel<<<(NTOK * 32 + 255) / 256, 256>>>(h, sgw);
    combine_kernel<<<NTOK, 256>>>(out);
}